// round 14
// baseline (speedup 1.0000x reference)
#include <cuda_runtime.h>
#include <cuda_bf16.h>
#include <math.h>
#include <cstdint>

#define BB 512
#define TT 200
#define HH 128
#define VV 100001
#define G3 384
#define M_TOTAL (BB*TT)   // 102400

// ---------------- scratch ----------------
__device__ float d_embT[(size_t)VV*HH];            // (V, H) = emb_W^T
__device__ __nv_bfloat16 d_xhi[(size_t)M_TOTAL*HH];
__device__ __nv_bfloat16 d_xlo[(size_t)M_TOTAL*HH];
__device__ __nv_bfloat16 d_whi[G3*HH];
__device__ __nv_bfloat16 d_wlo[G3*HH];
__device__ float d_gi [(size_t)M_TOTAL*G3];        // x @ Wih^T + bih + bhh
__device__ float d_hs [(size_t)M_TOTAL*HH];        // GRU hidden states

// ---------------- packed f32x2 helpers ----------------
#define FMA2(acc, a, b) asm("fma.rn.f32x2 %0, %1, %2, %0;" : "+l"(acc) : "l"(a), "l"(b))
__device__ __forceinline__ float f2sum(unsigned long long v) {
    float lo, hi;
    asm("mov.b64 {%0,%1}, %2;" : "=f"(lo), "=f"(hi) : "l"(v));
    return lo + hi;
}

// fast sigmoid / tanh via MUFU
__device__ __forceinline__ float sigf(float x) {
    float e, r;
    asm("ex2.approx.f32 %0, %1;" : "=f"(e) : "f"(-1.4426950408889634f * x));
    asm("rcp.approx.f32 %0, %1;" : "=f"(r) : "f"(1.0f + e));
    return r;
}
__device__ __forceinline__ float tanhfast(float x) {
    return fmaf(2.0f, sigf(2.0f * x), -1.0f);
}

// ---------------- warp MMA helpers ----------------
__device__ __forceinline__ uint32_t smem_u32(const void* p) {
    uint32_t a;
    asm("{ .reg .u64 t; cvta.to.shared.u64 t, %1; cvt.u32.u64 %0, t; }"
        : "=r"(a) : "l"(p));
    return a;
}
__device__ __forceinline__ void ldsm4(uint32_t* r, uint32_t addr) {
    asm volatile("ldmatrix.sync.aligned.m8n8.x4.shared.b16 {%0,%1,%2,%3}, [%4];"
        : "=r"(r[0]), "=r"(r[1]), "=r"(r[2]), "=r"(r[3]) : "r"(addr));
}
__device__ __forceinline__ void mma16816(float* d, const uint32_t* a, const uint32_t* b) {
    asm volatile("mma.sync.aligned.m16n8k16.row.col.f32.bf16.bf16.f32 "
        "{%0,%1,%2,%3}, {%4,%5,%6,%7}, {%8,%9}, {%0,%1,%2,%3};"
        : "+f"(d[0]), "+f"(d[1]), "+f"(d[2]), "+f"(d[3])
        : "r"(a[0]), "r"(a[1]), "r"(a[2]), "r"(a[3]), "r"(b[0]), "r"(b[1]));
}

// ---------------- block-wide sum over 128 threads ----------------
__device__ __forceinline__ float blocksum128(float v, float* sb) {
    #pragma unroll
    for (int o = 16; o; o >>= 1) v += __shfl_xor_sync(0xffffffffu, v, o);
    if ((threadIdx.x & 31) == 0) sb[threadIdx.x >> 5] = v;
    __syncthreads();
    float r = sb[0] + sb[1] + sb[2] + sb[3];
    __syncthreads();
    return r;
}

// ---------------- K0: combined prep (emb transpose + Wih split) ----------------
// grid (3126, 5), 256 threads flat. y<4: 32x32 transpose tile of emb_W (128 x VV).
// y==4: Wih bf16 hi/lo split (first 192 x-blocks).
__global__ void prep_kernel(const float* __restrict__ embW, float* __restrict__ embT,
                            const float* __restrict__ wih,
                            __nv_bfloat16* __restrict__ whi, __nv_bfloat16* __restrict__ wlo) {
    int tid = threadIdx.x;
    if (blockIdx.y < 4) {
        __shared__ float tile[32][33];
        int c0 = blockIdx.x * 32, r0 = blockIdx.y * 32;
        int tx = tid & 31, ty = tid >> 5;   // (32, 8)
        #pragma unroll
        for (int j = 0; j < 32; j += 8) {
            int r = r0 + ty + j, c = c0 + tx;
            if (c < VV) tile[ty + j][tx] = embW[(size_t)r * VV + c];
        }
        __syncthreads();
        #pragma unroll
        for (int j = 0; j < 32; j += 8) {
            int r = r0 + tx, c = c0 + ty + j;
            if (c < VV) embT[(size_t)c * HH + r] = tile[tx][ty + j];
        }
    } else {
        int i = blockIdx.x * 256 + tid;
        if (i < G3 * HH) {
            float v = wih[i];
            __nv_bfloat16 h = __float2bfloat16(v);
            whi[i] = h;
            wlo[i] = __float2bfloat16(v - __bfloat162float(h));
        }
    }
}

// ---------------- K1: embedding gather + LayerNorm1 -> bf16 hi/lo ----------------
__global__ void embed_ln1(const int* __restrict__ seqs,
                          const float* __restrict__ g1, const float* __restrict__ b1,
                          __nv_bfloat16* __restrict__ xhi, __nv_bfloat16* __restrict__ xlo) {
    __shared__ float sb[4];
    int idx = blockIdx.x;            // b*TT + t
    int b = idx / TT, t = idx - b * TT;
    int tid = threadIdx.x;           // 128
    int tok = seqs[b * (TT + 1) + t];
    float e  = d_embT[(size_t)tok * HH + tid];
    float mu = blocksum128(e, sb) * (1.0f / HH);
    float d  = e - mu;
    float var = blocksum128(d * d, sb) * (1.0f / HH);
    float xn = d * rsqrtf(var + 1e-8f) * g1[tid] + b1[tid];
    __nv_bfloat16 h = __float2bfloat16(xn);
    xhi[(size_t)idx * HH + tid] = h;
    xlo[(size_t)idx * HH + tid] = __float2bfloat16(xn - __bfloat162float(h));
}

// ---------------- K2: warp-MMA GEMM  gi = x @ Wih^T + (bih+bhh) ----------------
// 256 threads = 8 warps (4m x 2n), tile M=128 x N=64, warp 32x32, K=128.
// 2 CTAs/SM (104.7 KB smem each) -> staging/epilogue of one CTA overlaps MMA
// of the other. Split bf16: D = Ah*Bh + Ah*Bl + Al*Bh.
// Pitch 272 B: 16B-aligned rows; 16B-chunk stride 17 (odd) -> ldmatrix phases
// conflict-free. Per kstep: 8 ldmatrix.x4 feed 24 MMA (3:1).
#define PAB  272
#define OFF_AH   0
#define OFF_AL   (128 * PAB)              // 34816
#define OFF_BH   (2 * 128 * PAB)          // 69632
#define OFF_BL   (OFF_BH + 64 * PAB)      // 87040
#define OFF_BIAS (OFF_BH + 2 * 64 * PAB)  // 104448
#define GEMM_SMEM (OFF_BIAS + 256)        // 104704

__global__ __launch_bounds__(256, 2)
void gemm_tc(const __nv_bfloat16* __restrict__ xhi, const __nv_bfloat16* __restrict__ xlo,
             const __nv_bfloat16* __restrict__ whi, const __nv_bfloat16* __restrict__ wlo,
             const float* __restrict__ bih, const float* __restrict__ bhh,
             float* __restrict__ gi) {
    extern __shared__ char sm[];
    uint32_t smb = smem_u32(sm);
    float* biassh = (float*)(sm + OFF_BIAS);
    int tid = threadIdx.x;
    int n0 = blockIdx.x * 64;       // fast dim = n -> A tiles L2-reused (6 share)
    int m0 = blockIdx.y * 128;

    // stage A (hi+lo): 128 rows x 16 chunks of 16B
    #pragma unroll
    for (int i = tid; i < 128 * 16; i += 256) {
        int row = i >> 4, ch = i & 15;
        size_t ga = ((size_t)(m0 + row)) * HH + ch * 8;
        uint32_t so = (uint32_t)row * PAB + ch * 16;
        *(uint4*)(sm + OFF_AH + so) = *(const uint4*)&xhi[ga];
        *(uint4*)(sm + OFF_AL + so) = *(const uint4*)&xlo[ga];
    }
    // stage B (hi+lo): 64 n-rows x 16 chunks
    #pragma unroll
    for (int i = tid; i < 64 * 16; i += 256) {
        int row = i >> 4, ch = i & 15;
        size_t ga = ((size_t)(n0 + row)) * HH + ch * 8;
        uint32_t so = (uint32_t)row * PAB + ch * 16;
        *(uint4*)(sm + OFF_BH + so) = *(const uint4*)&whi[ga];
        *(uint4*)(sm + OFF_BL + so) = *(const uint4*)&wlo[ga];
    }
    for (int i = tid; i < 64; i += 256) biassh[i] = bih[n0 + i] + bhh[n0 + i];
    __syncthreads();

    int wid = tid >> 5, l = tid & 31;
    int m_off = (wid >> 1) * 32;     // warp m offset (0,32,64,96)
    int nw    = (wid & 1) * 32;      // warp n offset (0,32)

    uint32_t a_lane = smb + (uint32_t)(m_off + (l & 15)) * PAB + (uint32_t)(l >> 4) * 16;
    uint32_t b_lane = smb + (uint32_t)(nw + (l & 7) + ((l >= 16) ? 8 : 0)) * PAB
                          + (uint32_t)((l & 8) ? 16 : 0);

    float acc[2][4][4];
    #pragma unroll
    for (int mt = 0; mt < 2; mt++)
        #pragma unroll
        for (int nt = 0; nt < 4; nt++)
            #pragma unroll
            for (int r = 0; r < 4; r++) acc[mt][nt][r] = 0.f;

    #pragma unroll 1
    for (int ks = 0; ks < 8; ks++) {
        uint32_t ko = ks * 32;
        uint32_t afH[2][4], afL[2][4], bfH[2][4], bfL[2][4];
        #pragma unroll
        for (int mt = 0; mt < 2; mt++) {
            ldsm4(afH[mt], a_lane + OFF_AH + ko + mt * 16 * PAB);
            ldsm4(afL[mt], a_lane + OFF_AL + ko + mt * 16 * PAB);
        }
        #pragma unroll
        for (int np = 0; np < 2; np++) {
            ldsm4(bfH[np], b_lane + OFF_BH + ko + np * 16 * PAB);
            ldsm4(bfL[np], b_lane + OFF_BL + ko + np * 16 * PAB);
        }
        #pragma unroll
        for (int mt = 0; mt < 2; mt++)
            #pragma unroll
            for (int nt = 0; nt < 4; nt++) {
                mma16816(acc[mt][nt], afH[mt], &bfH[nt >> 1][(nt & 1) * 2]);
                mma16816(acc[mt][nt], afH[mt], &bfL[nt >> 1][(nt & 1) * 2]);
                mma16816(acc[mt][nt], afL[mt], &bfH[nt >> 1][(nt & 1) * 2]);
            }
    }

    // epilogue: add bias, store float2 pairs
    #pragma unroll
    for (int mt = 0; mt < 2; mt++) {
        #pragma unroll
        for (int nt = 0; nt < 4; nt++) {
            int m1 = m0 + m_off + mt * 16 + (l >> 2);
            int nn = nw + nt * 8 + 2 * (l & 3);
            float b0 = biassh[nn], b1 = biassh[nn + 1];
            float2 s0 = make_float2(acc[mt][nt][0] + b0, acc[mt][nt][1] + b1);
            float2 s1 = make_float2(acc[mt][nt][2] + b0, acc[mt][nt][3] + b1);
            *(float2*)&gi[(size_t)m1 * G3 + n0 + nn]       = s0;
            *(float2*)&gi[(size_t)(m1 + 8) * G3 + n0 + nn] = s1;
        }
    }
}

// ---------------- K3: GRU recurrence (unchanged) ----------------
#define HP   144
#define GHPS 1544
__global__ __launch_bounds__(512)
void gru_rec(const float* __restrict__ gi, const float* __restrict__ Whh,
             float* __restrict__ hs) {
    __shared__ float hsh[4 * HP];
    __shared__ float ghp[4 * GHPS];
    int tid = threadIdx.x;
    int kp = tid & 3, rp = tid >> 2;
    int s0 = blockIdx.x * 4;

    unsigned long long w[48];
    {
        const float* wb = Whh + (size_t)rp * 128 + kp * 32;
        #pragma unroll
        for (int r = 0; r < 3; r++) {
            const ulonglong2* p = (const ulonglong2*)(wb + (size_t)r * 128 * 128);
            #pragma unroll
            for (int i = 0; i < 8; i++) {
                ulonglong2 v = p[i];
                w[r * 16 + 2 * i]     = v.x;
                w[r * 16 + 2 * i + 1] = v.y;
            }
        }
    }

    int su = tid >> 7, ju = tid & 127;
    const float* gp = gi + ((size_t)(s0 + su) * TT) * G3 + ju;
    float* hp = hs + ((size_t)(s0 + su) * TT) * HH + ju;
    float hreg = 0.f;

    for (int i = tid; i < 4 * HP; i += 512) hsh[i] = 0.f;
    __syncthreads();

    float* gout = &ghp[kp * GHPS + rp];

    for (int t = 0; t < TT; t++) {
        float ir  = gp[0];
        float iz  = gp[128];
        float inn = gp[256];

        #pragma unroll 1
        for (int seq = 0; seq < 4; seq++) {
            unsigned long long a0 = 0ull, a1 = 0ull, a2 = 0ull;
            const ulonglong2* hq = (const ulonglong2*)&hsh[seq * HP + kp * 36];
            #pragma unroll
            for (int i = 0; i < 8; i++) {
                ulonglong2 hv = hq[i];
                FMA2(a0, w[2 * i],      hv.x); FMA2(a0, w[2 * i + 1],      hv.y);
                FMA2(a1, w[16 + 2 * i], hv.x); FMA2(a1, w[16 + 2 * i + 1], hv.y);
                FMA2(a2, w[32 + 2 * i], hv.x); FMA2(a2, w[32 + 2 * i + 1], hv.y);
            }
            float* go = gout + seq * 384;
            go[0]   = f2sum(a0);
            go[128] = f2sum(a1);
            go[256] = f2sum(a2);
        }
        __syncthreads();

        {
            int u = su * 384 + ju;
            const float* g0 = &ghp[u];
            const float* g1 = &ghp[GHPS + u];
            const float* g2 = &ghp[2 * GHPS + u];
            const float* g3 = &ghp[3 * GHPS + u];
            float hr = (g0[0]   + g1[0])   + (g2[0]   + g3[0]);
            float hz = (g0[128] + g1[128]) + (g2[128] + g3[128]);
            float hn = (g0[256] + g1[256]) + (g2[256] + g3[256]);
            float r = sigf(ir + hr);
            float z = sigf(iz + hz);
            float n = tanhfast(inn + r * hn);
            float hnew = (1.f - z) * n + z * hreg;
            hreg = hnew;
            hsh[su * HP + (ju >> 5) * 36 + (ju & 31)] = hnew;
            *hp = hnew;
            gp += G3;
            hp += HH;
        }
        __syncthreads();
    }
}

// ---------------- K4: LayerNorm2 + pos/neg dot products ----------------
__global__ void final_logits(const int* __restrict__ seqs, const int* __restrict__ negs,
                             const float* __restrict__ g2, const float* __restrict__ b2,
                             float* __restrict__ out) {
    __shared__ float sb[4];
    int idx = blockIdx.x;
    int b = idx / TT, t = idx - b * TT;
    int tid = threadIdx.x;          // 128
    float v  = d_hs[(size_t)idx * HH + tid];
    float mu = blocksum128(v, sb) * (1.0f / HH);
    float d  = v - mu;
    float var = blocksum128(d * d, sb) * (1.0f / HH);
    float ln = d * rsqrtf(var + 1e-8f) * g2[tid] + b2[tid];

    int pt = seqs[b * (TT + 1) + t + 1];
    int nt = negs[b * (TT + 1) + t + 1];
    float pv = ln * d_embT[(size_t)pt * HH + tid];
    float nv = ln * d_embT[(size_t)nt * HH + tid];
    float ps = blocksum128(pv, sb);
    float ns = blocksum128(nv, sb);
    if (tid == 0) {
        out[idx]           = ps;
        out[M_TOTAL + idx] = ns;
    }
}

// ---------------- launch ----------------
extern "C" void kernel_launch(void* const* d_in, const int* in_sizes, int n_in,
                              void* d_out, int out_size) {
    const int*   input_seqs = (const int*)  d_in[0];
    const int*   negs       = (const int*)  d_in[1];
    const float* emb_W      = (const float*)d_in[2];
    const float* Wih        = (const float*)d_in[3];
    const float* Whh        = (const float*)d_in[4];
    const float* bih        = (const float*)d_in[5];
    const float* bhh        = (const float*)d_in[6];
    const float* ln1_g      = (const float*)d_in[7];
    const float* ln1_b      = (const float*)d_in[8];
    const float* ln2_g      = (const float*)d_in[9];
    const float* ln2_b      = (const float*)d_in[10];
    float* out = (float*)d_out;

    float* p_embT; cudaGetSymbolAddress((void**)&p_embT, d_embT);
    __nv_bfloat16* p_xhi; cudaGetSymbolAddress((void**)&p_xhi, d_xhi);
    __nv_bfloat16* p_xlo; cudaGetSymbolAddress((void**)&p_xlo, d_xlo);
    __nv_bfloat16* p_whi; cudaGetSymbolAddress((void**)&p_whi, d_whi);
    __nv_bfloat16* p_wlo; cudaGetSymbolAddress((void**)&p_wlo, d_wlo);
    float* p_gi;   cudaGetSymbolAddress((void**)&p_gi,   d_gi);
    float* p_hs;   cudaGetSymbolAddress((void**)&p_hs,   d_hs);

    // launch 0: prep (transpose + wsplit). launch 1: embed_ln1.
    // launch 2: gemm_tc. launch 3: gru_rec (<- ncu capture slot). launch 4: final.
    prep_kernel<<<dim3((VV + 31) / 32, 5), 256>>>(emb_W, p_embT, Wih, p_whi, p_wlo);

    embed_ln1<<<M_TOTAL, 128>>>(input_seqs, ln1_g, ln1_b, p_xhi, p_xlo);

    cudaFuncSetAttribute(gemm_tc, cudaFuncAttributeMaxDynamicSharedMemorySize, GEMM_SMEM);
    gemm_tc<<<dim3(G3 / 64, M_TOTAL / 128), 256, GEMM_SMEM>>>(
        p_xhi, p_xlo, p_whi, p_wlo, bih, bhh, p_gi);

    gru_rec<<<BB / 4, 512>>>(p_gi, Whh, p_hs);

    final_logits<<<M_TOTAL, 128>>>(input_seqs, negs, ln2_g, ln2_b, out);
}